// round 5
// baseline (speedup 1.0000x reference)
#include <cuda_runtime.h>
#include <math.h>

// B=8, C=128, N=8192, K=9, PAD=4, DIL=1, STR=1, L=N
#define Bv 8
#define Cv 128
#define Nv 8192
#define Kv 9
#define HALF_K 4
#define TL 128            // l positions per block tile
#define THREADS 256
#define CPB 32            // channels per block
#define XROW (TL + 8)     // 136 floats per staged channel row
#define NQ (XROW / 4)     // 34 float4 per row

__global__ __launch_bounds__(THREADS, 4)
void swconv_kernel(const float* __restrict__ x,
                   const float* __restrict__ coords,
                   const float* __restrict__ sigma,
                   const float* __restrict__ weight,
                   float* __restrict__ out)
{
    __shared__ float xs[CPB][XROW];   // staged x tile (with K-1 halo)
    __shared__ float dwT[Kv][TL];     // [k][l] transposed for aligned float4 reads
    __shared__ float ws[CPB * Kv];

    const int b     = blockIdx.y;
    const int l0g   = blockIdx.x * TL;
    const int cbase = blockIdx.z * CPB;
    const int tid   = threadIdx.x;

    const bool interior = (l0g >= HALF_K) && (l0g + TL + HALF_K <= Nv);

    // ---- phase 0: stage x tile into smem. All loads independent -> high MLP ----
    if (interior) {
        // 136-float rows start at l0g-4: byte offset (l0g-4)*4 is 16B-aligned
        #pragma unroll 5
        for (int i = tid; i < CPB * NQ; i += THREADS) {
            const int ch = i / NQ;
            const int q  = i - ch * NQ;
            const float4 v = *reinterpret_cast<const float4*>(
                x + (b * Cv + cbase + ch) * Nv + l0g - HALF_K + q * 4);
            *reinterpret_cast<float4*>(&xs[ch][q * 4]) = v;
        }
    } else {
        for (int i = tid; i < CPB * XROW; i += THREADS) {
            const int ch  = i / XROW;
            const int j   = i - ch * XROW;
            const int idx = l0g - HALF_K + j;
            xs[ch][j] = (idx >= 0 && idx < Nv)
                        ? x[(b * Cv + cbase + ch) * Nv + idx] : 0.0f;
        }
    }

    // ---- weights slice ----
    for (int i = tid; i < CPB * Kv; i += THREADS)
        ws[i] = weight[cbase * Kv + i];

    // ---- phase 1: dw[l][k], split across all 256 threads (k halves) ----
    {
        const int l_loc = tid & (TL - 1);
        const int khalf = tid >> 7;           // 0 -> k 0..4, 1 -> k 5..8
        const int l     = l0g + l_loc;
        const float* cb = coords + b * 3 * Nv;
        const float cx = cb[l];
        const float cy = cb[Nv + l];
        const float cz = cb[2 * Nv + l];
        const float inv_sig = 1.0f / sigma[0];
        const int k0 = khalf ? 5 : 0;
        const int k1 = khalf ? Kv : 5;
        for (int k = k0; k < k1; k++) {
            const int idx = l + k - HALF_K;
            float dx, dy, dz;
            if (idx >= 0 && idx < Nv) {
                dx = cb[idx]          - cx;
                dy = cb[Nv + idx]     - cy;
                dz = cb[2 * Nv + idx] - cz;
            } else {
                dx = -cx; dy = -cy; dz = -cz;   // zero-padded coords
            }
            const float sq   = dx * dx + dy * dy + dz * dz;
            const float dist = (sq > 0.0f) ? sqrtf(sq) : 0.0f;
            dwT[k][l_loc] = fmaxf(1.0f - dist * inv_sig, 0.0f);
        }
    }
    __syncthreads();

    // ---- phase 2: weighted depthwise conv, all operands in smem ----
    const int lane = tid & 31;
    const int w_id = tid >> 5;          // warp -> channel offset within pass
    const int lq   = lane * 4;          // local l of first output
    const int lg   = l0g + lq;          // global l

    // distance weights for this thread's 4 outputs, register-cached,
    // reused across all 4 channel iterations
    float4 dq[Kv];
    #pragma unroll
    for (int k = 0; k < Kv; k++)
        dq[k] = *reinterpret_cast<const float4*>(&dwT[k][lq]);

    #pragma unroll
    for (int it = 0; it < CPB / 8; ++it) {
        const int cof = it * 8 + w_id;
        // output local l = lq..lq+3; tap k of local l -> xs[cof][l + k]
        const float* xr = &xs[cof][lq];
        const float4 a = *reinterpret_cast<const float4*>(xr);
        const float4 m = *reinterpret_cast<const float4*>(xr + 4);
        const float4 r = *reinterpret_cast<const float4*>(xr + 8);
        float xv[12] = { a.x, a.y, a.z, a.w,
                         m.x, m.y, m.z, m.w,
                         r.x, r.y, r.z, r.w };

        const float* wc = &ws[cof * Kv];
        float4 acc = make_float4(0.f, 0.f, 0.f, 0.f);
        #pragma unroll
        for (int k = 0; k < Kv; k++) {
            const float wk = wc[k];     // broadcast across warp
            acc.x = fmaf(xv[k + 0] * dq[k].x, wk, acc.x);
            acc.y = fmaf(xv[k + 1] * dq[k].y, wk, acc.y);
            acc.z = fmaf(xv[k + 2] * dq[k].z, wk, acc.z);
            acc.w = fmaf(xv[k + 3] * dq[k].w, wk, acc.w);
        }
        *reinterpret_cast<float4*>(out + (b * Cv + cbase + cof) * Nv + lg) = acc;
    }
}

extern "C" void kernel_launch(void* const* d_in, const int* in_sizes, int n_in,
                              void* d_out, int out_size)
{
    const float* x      = (const float*)d_in[0];
    const float* coords = (const float*)d_in[1];
    const float* sigma  = (const float*)d_in[2];
    const float* weight = (const float*)d_in[3];
    float* out = (float*)d_out;

    dim3 grid(Nv / TL, Bv, Cv / CPB);   // (64, 8, 4)
    swconv_kernel<<<grid, THREADS>>>(x, coords, sigma, weight, out);
}

// round 8
// speedup vs baseline: 1.0447x; 1.0447x over previous
#include <cuda_runtime.h>
#include <cuda_pipeline_primitives.h>
#include <math.h>
#include <stdint.h>

// B=8, C=128, N=8192, K=9, PAD=4, DIL=1, STR=1, L=N
#define Bv 8
#define Cv 128
#define Nv 8192
#define Kv 9
#define HALF_K 4
#define TL 128             // l positions per tile
#define THREADS 256
#define CPB 32             // channels per block
#define TILES 4            // tiles per block
#define STRIP (TL * TILES) // 512
#define XROW (TL + 8)      // 136 floats per staged row (4 halo each side)
#define NQ (XROW / 4)      // 34 quads per row

// Issue async staging for one tile (x rows + coords rows). OOB quads are
// exactly 4-aligned (pad=4), so a quad is either fully in-range or fully out.
__device__ __forceinline__ void stage_tile(
    float (*xsb)[XROW], float (*csb)[XROW],
    const float* __restrict__ xb, const float* __restrict__ cb,
    int l0, int tid)
{
    #pragma unroll 5
    for (int i = tid; i < CPB * NQ; i += THREADS) {
        const int ch = i / NQ;
        const int q  = i - ch * NQ;
        const int g0 = l0 - HALF_K + q * 4;
        if (g0 >= 0 && g0 + 4 <= Nv) {
            __pipeline_memcpy_async(&xsb[ch][q * 4], xb + (size_t)ch * Nv + g0, 16);
        } else {
            *reinterpret_cast<float4*>(&xsb[ch][q * 4]) = make_float4(0.f, 0.f, 0.f, 0.f);
        }
    }
    for (int j = tid; j < 3 * NQ; j += THREADS) {
        const int d  = j / NQ;
        const int q  = j - d * NQ;
        const int g0 = l0 - HALF_K + q * 4;
        if (g0 >= 0 && g0 + 4 <= Nv) {
            __pipeline_memcpy_async(&csb[d][q * 4], cb + (size_t)d * Nv + g0, 16);
        } else {
            *reinterpret_cast<float4*>(&csb[d][q * 4]) = make_float4(0.f, 0.f, 0.f, 0.f);
        }
    }
}

__global__ __launch_bounds__(THREADS, 4)
void swconv_kernel(const float* __restrict__ x,
                   const float* __restrict__ coords,
                   const float* __restrict__ sigma,
                   const float* __restrict__ weight,
                   float* __restrict__ out)
{
    __shared__ float xs[2][CPB][XROW];   // 34.0 KB double-buffered x tiles
    __shared__ float cs[2][3][XROW];     //  3.2 KB double-buffered coords
    __shared__ float dwT[2][Kv][TL];     //  9.0 KB double-buffered dist weights
    __shared__ float ws[CPB * Kv];       //  1.1 KB weights slice

    const int b     = blockIdx.y;
    const int cbase = blockIdx.z * CPB;
    const int l_strip = blockIdx.x * STRIP;
    const int tid   = threadIdx.x;

    const float* xb = x + ((size_t)b * Cv + cbase) * Nv;
    const float* cb = coords + (size_t)b * 3 * Nv;

    for (int i = tid; i < CPB * Kv; i += THREADS)
        ws[i] = weight[cbase * Kv + i];
    const float inv_sig = 1.0f / sigma[0];

    // prologue: kick off tile 0's loads
    stage_tile(xs[0], cs[0], xb, cb, l_strip, tid);
    __pipeline_commit();

    const int lane  = tid & 31;
    const int w_id  = tid >> 5;          // warp -> channel offset
    const int lq    = lane * 4;          // local l of first output
    const int l_loc = tid & (TL - 1);
    const int khalf = tid >> 7;          // 0 -> k 0..4, 1 -> k 5..8
    const int k0 = khalf ? 5 : 0;
    const int k1 = khalf ? Kv : 5;

    for (int t = 0; t < TILES; ++t) {
        const int buf = t & 1;
        const int l0  = l_strip + t * TL;

        __pipeline_wait_prior(0);   // tile t's data landed (in flight during t-1)
        __syncthreads();            // all threads done with buf^1 reads (tile t-1)

        // overlap: tile t+1's loads fly during dw-compute + FMA of tile t
        if (t + 1 < TILES)
            stage_tile(xs[buf ^ 1], cs[buf ^ 1], xb, cb, l0 + TL, tid);
        __pipeline_commit();

        // distance weights for tile t, from smem coords (k-halves across 256 thr)
        {
            const float cx = cs[buf][0][l_loc + HALF_K];
            const float cy = cs[buf][1][l_loc + HALF_K];
            const float cz = cs[buf][2][l_loc + HALF_K];
            for (int k = k0; k < k1; k++) {
                const float dx = cs[buf][0][l_loc + k] - cx;
                const float dy = cs[buf][1][l_loc + k] - cy;
                const float dz = cs[buf][2][l_loc + k] - cz;
                const float sq = dx * dx + dy * dy + dz * dz;
                const float dist = (sq > 0.0f) ? sqrtf(sq) : 0.0f;
                dwT[buf][k][l_loc] = fmaxf(1.0f - dist * inv_sig, 0.0f);
            }
        }
        __syncthreads();

        // register-cache this thread's dw quads, reused over 4 channel iters
        float4 dq[Kv];
        #pragma unroll
        for (int k = 0; k < Kv; k++)
            dq[k] = *reinterpret_cast<const float4*>(&dwT[buf][k][lq]);

        #pragma unroll
        for (int it = 0; it < CPB / 8; ++it) {
            const int cof = it * 8 + w_id;
            const float* xr = &xs[buf][cof][lq];
            const float4 a = *reinterpret_cast<const float4*>(xr);
            const float4 m = *reinterpret_cast<const float4*>(xr + 4);
            const float4 r = *reinterpret_cast<const float4*>(xr + 8);
            float xv[12] = { a.x, a.y, a.z, a.w,
                             m.x, m.y, m.z, m.w,
                             r.x, r.y, r.z, r.w };

            const float* wc = &ws[cof * Kv];
            float4 acc = make_float4(0.f, 0.f, 0.f, 0.f);
            #pragma unroll
            for (int k = 0; k < Kv; k++) {
                const float wk = wc[k];      // warp-uniform
                acc.x = fmaf(xv[k + 0] * dq[k].x, wk, acc.x);
                acc.y = fmaf(xv[k + 1] * dq[k].y, wk, acc.y);
                acc.z = fmaf(xv[k + 2] * dq[k].z, wk, acc.z);
                acc.w = fmaf(xv[k + 3] * dq[k].w, wk, acc.w);
            }
            *reinterpret_cast<float4*>(
                out + ((size_t)b * Cv + cbase + cof) * Nv + l0 + lq) = acc;
        }
    }
}

extern "C" void kernel_launch(void* const* d_in, const int* in_sizes, int n_in,
                              void* d_out, int out_size)
{
    const float* x      = (const float*)d_in[0];
    const float* coords = (const float*)d_in[1];
    const float* sigma  = (const float*)d_in[2];
    const float* weight = (const float*)d_in[3];
    float* out = (float*)d_out;

    dim3 grid(Nv / STRIP, Bv, Cv / CPB);   // (16, 8, 4) = 512 blocks
    swconv_kernel<<<grid, THREADS>>>(x, coords, sigma, weight, out);
}